// round 7
// baseline (speedup 1.0000x reference)
#include <cuda_runtime.h>
#include <cuda_bf16.h>
#include <math.h>

#define N_ROIS 128
#define BEV_H 188
#define BEV_W 188
#define BEV_C 256
#define NCELLS (BEV_H * BEV_W)      // 35344 cells, key = yclamp*188 + xclamp
#define MAXN 262144

// ---- scratch (static device globals; no runtime allocation) ----
__device__ float4 g_wt[MAXN];        // bilinear weights per point
__device__ int    g_key[MAXN];       // cell key, or -1 if masked out
__device__ int    g_hist[NCELLS];    // masked-point count per cell
__device__ int    g_offs[NCELLS];    // exclusive-scan offsets (mutated by scatter)
__device__ int    g_sorted[MAXN];    // point ids grouped by cell

// ================= 1. init =================
__global__ void k_init()
{
    int i = blockIdx.x * blockDim.x + threadIdx.x;
    if (i < NCELLS) g_hist[i] = 0;
}

// ================= 2. phase 1: argmin + mask + params =================
__global__ void __launch_bounds__(256)
k_phase1(const float* __restrict__ points,
         const float* __restrict__ rois, int n)
{
    __shared__ float4 s_roi[N_ROIS];   // (cx, cy, cz, ||dims/2||+2.4)

    if (threadIdx.x < N_ROIS) {
        const float* rp = rois + threadIdx.x * 7;
        const float hl = rp[3] * 0.5f;
        const float hw = rp[4] * 0.5f;
        const float hh = rp[5] * 0.5f;
        const float rad = sqrtf(hl * hl + hw * hw + hh * hh) + 2.4f;
        s_roi[threadIdx.x] = make_float4(rp[0], rp[1], rp[2], rad);
    }
    __syncthreads();

    const int p = blockIdx.x * blockDim.x + threadIdx.x;
    if (p >= n) return;

    const float px = points[p * 3 + 0];
    const float py = points[p * 3 + 1];
    const float pz = points[p * 3 + 2];

    float best = INFINITY;
    int bidx = 0;
    #pragma unroll 4
    for (int r = 0; r < N_ROIS; r++) {
        const float4 q = s_roi[r];          // warp-broadcast LDS.128
        const float dx = px - q.x;
        const float dy = py - q.y;
        const float dz = pz - q.z;
        const float d2 = dx * dx + dy * dy + dz * dz;
        if (d2 < best) { best = d2; bidx = r; }   // '<' -> first occurrence
    }
    const bool mask = sqrtf(best) < s_roi[bidx].w;

    if (!mask) {
        g_key[p] = -1;
        return;
    }

    // bit-faithful coords: two fp32 divides, floor, clamp
    const float xi = (px - 0.0f)   / 0.05f / 8.0f;
    const float yi = (py - -40.0f) / 0.05f / 8.0f;
    const int xf = (int)floorf(xi);
    const int yf = (int)floorf(yi);
    const int x0 = min(max(xf,     0), BEV_W - 1);
    const int x1 = min(max(xf + 1, 0), BEV_W - 1);
    const int y0 = min(max(yf,     0), BEV_H - 1);
    const int y1 = min(max(yf + 1, 0), BEV_H - 1);

    const float x0f = (float)x0, x1f = (float)x1;
    const float y0f = (float)y0, y1f = (float)y1;
    float4 wt;
    wt.x = (x1f - xi) * (y1f - yi);   // wa
    wt.y = (x1f - xi) * (yi - y0f);   // wb
    wt.z = (xi - x0f) * (y1f - yi);   // wc
    wt.w = (xi - x0f) * (yi - y0f);   // wd
    g_wt[p] = wt;

    // cell key: clamped floor coords fully determine (x0,x1,y0,y1)
    const int key = y0 * BEV_W + x0;
    g_key[p] = key;
    atomicAdd(&g_hist[key], 1);
}

// ================= 3. single-block exclusive scan over NCELLS =================
__global__ void __launch_bounds__(1024)
k_scan()
{
    __shared__ int s[1024];
    const int t = threadIdx.x;
    const int CH = (NCELLS + 1023) / 1024;   // 35
    const int base = t * CH;

    int sum = 0;
    #pragma unroll
    for (int i = 0; i < CH; i++) {
        const int idx = base + i;
        if (idx < NCELLS) sum += g_hist[idx];
    }
    s[t] = sum;
    __syncthreads();
    // Hillis-Steele inclusive scan (uniform control flow)
    for (int off = 1; off < 1024; off <<= 1) {
        int v = (t >= off) ? s[t - off] : 0;
        __syncthreads();
        s[t] += v;
        __syncthreads();
    }
    int run = (t > 0) ? s[t - 1] : 0;        // exclusive prefix
    #pragma unroll
    for (int i = 0; i < CH; i++) {
        const int idx = base + i;
        if (idx < NCELLS) {
            const int h = g_hist[idx];
            g_offs[idx] = run;
            run += h;
        }
    }
}

// ================= 4. scatter (counting sort by cell) =================
__global__ void __launch_bounds__(256)
k_scatter(int n)
{
    const int p = blockIdx.x * blockDim.x + threadIdx.x;
    if (p >= n) return;
    const int key = g_key[p];
    if (key < 0) return;
    const int pos = atomicAdd(&g_offs[key], 1);
    g_sorted[pos] = p;
}

// ================= 5. fused zero-fill + gather =================
// blocks [0, zb)        : warp per point  -> zero masked-out rows
// blocks [zb, zb + cb)  : warp per cell   -> corner rows in regs, serve points
__global__ void __launch_bounds__(256)
k_gather(const float* __restrict__ bev, float* __restrict__ out,
         int n, int zb)
{
    const int lane = threadIdx.x & 31;

    if (blockIdx.x < zb) {
        // ---- zero-fill region ----
        const int w = (blockIdx.x * 256 + threadIdx.x) >> 5;
        if (w >= n) return;
        if (g_key[w] >= 0) return;           // warp-uniform broadcast load
        float4* op = reinterpret_cast<float4*>(out + (size_t)w * BEV_C);
        const float4 z = make_float4(0.f, 0.f, 0.f, 0.f);
        __stcs(op + lane,      z);
        __stcs(op + lane + 32, z);
        return;
    }

    // ---- gather region ----
    const int c = (blockIdx.x - zb) * 8 + (threadIdx.x >> 5);
    if (c >= NCELLS) return;
    const int cnt = g_hist[c];
    if (cnt == 0) return;
    const int end   = g_offs[c];             // post-scatter == start + cnt
    const int start = end - cnt;

    const int xf = c % BEV_W;
    const int yf = c / BEV_W;
    const int x1 = min(xf + 1, BEV_W - 1);
    const int y1 = min(yf + 1, BEV_H - 1);

    const float4* A  = reinterpret_cast<const float4*>(bev + ((size_t)yf * BEV_W + xf) * BEV_C);
    const float4* B  = reinterpret_cast<const float4*>(bev + ((size_t)y1 * BEV_W + xf) * BEV_C);
    const float4* Cc = reinterpret_cast<const float4*>(bev + ((size_t)yf * BEV_W + x1) * BEV_C);
    const float4* D  = reinterpret_cast<const float4*>(bev + ((size_t)y1 * BEV_W + x1) * BEV_C);

    // load the 4 corner rows ONCE into registers (8 x float4 per lane)
    const float4 a0 = __ldcg(A  + lane);
    const float4 b0 = __ldcg(B  + lane);
    const float4 c0 = __ldcg(Cc + lane);
    const float4 d0 = __ldcg(D  + lane);
    const float4 a1 = __ldcg(A  + lane + 32);
    const float4 b1 = __ldcg(B  + lane + 32);
    const float4 c1 = __ldcg(Cc + lane + 32);
    const float4 d1 = __ldcg(D  + lane + 32);

    for (int i = start; i < end; i++) {
        const int    p  = g_sorted[i];       // warp-broadcast
        const float4 wv = g_wt[p];           // warp-broadcast

        float4 o0, o1;
        o0.x = a0.x * wv.x + b0.x * wv.y + c0.x * wv.z + d0.x * wv.w;
        o0.y = a0.y * wv.x + b0.y * wv.y + c0.y * wv.z + d0.y * wv.w;
        o0.z = a0.z * wv.x + b0.z * wv.y + c0.z * wv.z + d0.z * wv.w;
        o0.w = a0.w * wv.x + b0.w * wv.y + c0.w * wv.z + d0.w * wv.w;
        o1.x = a1.x * wv.x + b1.x * wv.y + c1.x * wv.z + d1.x * wv.w;
        o1.y = a1.y * wv.x + b1.y * wv.y + c1.y * wv.z + d1.y * wv.w;
        o1.z = a1.z * wv.x + b1.z * wv.y + c1.z * wv.z + d1.z * wv.w;
        o1.w = a1.w * wv.x + b1.w * wv.y + c1.w * wv.z + d1.w * wv.w;

        float4* op = reinterpret_cast<float4*>(out + (size_t)p * BEV_C);
        __stcs(op + lane,      o0);
        __stcs(op + lane + 32, o1);
    }
}

extern "C" void kernel_launch(void* const* d_in, const int* in_sizes, int n_in,
                              void* d_out, int out_size)
{
    const float* points = (const float*)d_in[0];
    const float* rois   = (const float*)d_in[1];
    const float* bev    = (const float*)d_in[2];
    float* out = (float*)d_out;

    const int n = in_sizes[0] / 3;   // fixed-shape problem; n <= MAXN

    const int zb = (n + 7) / 8;                 // zero-fill blocks (8 warps/blk)
    const int cb = (NCELLS + 7) / 8;            // cell blocks

    k_init<<<(NCELLS + 255) / 256, 256>>>();
    k_phase1<<<(n + 255) / 256, 256>>>(points, rois, n);
    k_scan<<<1, 1024>>>();
    k_scatter<<<(n + 255) / 256, 256>>>(n);
    k_gather<<<zb + cb, 256>>>(bev, out, n, zb);
}

// round 8
// speedup vs baseline: 1.2177x; 1.2177x over previous
#include <cuda_runtime.h>
#include <cuda_bf16.h>
#include <math.h>

#define N_ROIS 128
#define BEV_H 188
#define BEV_W 188
#define BEV_C 256
#define NCELLS (BEV_H * BEV_W)      // 35344 cells, key = y0*188 + x0 (clamped)
#define MAXN 262144
#define FULL 0xFFFFFFFFu

// ---- scratch (static device globals; no runtime allocation) ----
__device__ float4 g_wt[MAXN];        // weights, point order
__device__ float4 g_wts[MAXN];       // weights, sorted (cell-grouped) order
__device__ int    g_key[MAXN];       // cell key, or -1 if masked out
__device__ int    g_rank[MAXN];      // within-cell rank from phase1
__device__ int    g_hist[NCELLS];    // masked-point count per cell
__device__ int    g_offs[NCELLS];    // exclusive-scan offsets (NOT mutated)
__device__ int    g_sorted[MAXN];    // point ids grouped by cell

// ================= 1. init =================
__global__ void k_init()
{
    int i = blockIdx.x * blockDim.x + threadIdx.x;
    if (i < NCELLS) g_hist[i] = 0;
}

// ================= 2. phase 1: argmin + mask + params + rank =================
__global__ void __launch_bounds__(256)
k_phase1(const float* __restrict__ points,
         const float* __restrict__ rois, int n)
{
    __shared__ float4 s_roi[N_ROIS];   // (cx, cy, cz, ||dims/2||+2.4)

    if (threadIdx.x < N_ROIS) {
        const float* rp = rois + threadIdx.x * 7;
        const float hl = rp[3] * 0.5f;
        const float hw = rp[4] * 0.5f;
        const float hh = rp[5] * 0.5f;
        const float rad = sqrtf(hl * hl + hw * hw + hh * hh) + 2.4f;
        s_roi[threadIdx.x] = make_float4(rp[0], rp[1], rp[2], rad);
    }
    __syncthreads();

    const int p = blockIdx.x * blockDim.x + threadIdx.x;
    if (p >= n) return;

    const float px = points[p * 3 + 0];
    const float py = points[p * 3 + 1];
    const float pz = points[p * 3 + 2];

    float best = INFINITY;
    int bidx = 0;
    #pragma unroll 4
    for (int r = 0; r < N_ROIS; r++) {
        const float4 q = s_roi[r];          // warp-broadcast LDS.128
        const float dx = px - q.x;
        const float dy = py - q.y;
        const float dz = pz - q.z;
        const float d2 = dx * dx + dy * dy + dz * dz;
        if (d2 < best) { best = d2; bidx = r; }   // '<' -> first occurrence
    }
    const bool mask = sqrtf(best) < s_roi[bidx].w;

    if (!mask) {
        g_key[p] = -1;
        return;
    }

    // bit-faithful coords: two fp32 divides, floor, clamp
    const float xi = (px - 0.0f)   / 0.05f / 8.0f;
    const float yi = (py - -40.0f) / 0.05f / 8.0f;
    const int xf = (int)floorf(xi);
    const int yf = (int)floorf(yi);
    const int x0 = min(max(xf,     0), BEV_W - 1);
    const int x1 = min(max(xf + 1, 0), BEV_W - 1);
    const int y0 = min(max(yf,     0), BEV_H - 1);
    const int y1 = min(max(yf + 1, 0), BEV_H - 1);

    const float x0f = (float)x0, x1f = (float)x1;
    const float y0f = (float)y0, y1f = (float)y1;
    float4 wt;
    wt.x = (x1f - xi) * (y1f - yi);   // wa
    wt.y = (x1f - xi) * (yi - y0f);   // wb
    wt.z = (xi - x0f) * (y1f - yi);   // wc
    wt.w = (xi - x0f) * (yi - y0f);   // wd
    g_wt[p] = wt;

    const int key = y0 * BEV_W + x0;   // clamped floors determine corners
    g_key[p] = key;
    g_rank[p] = atomicAdd(&g_hist[key], 1);   // within-cell rank
}

// ================= 3. single-block exclusive scan over NCELLS =================
__global__ void __launch_bounds__(1024)
k_scan()
{
    __shared__ int s[1024];
    const int t = threadIdx.x;
    const int CH = (NCELLS + 1023) / 1024;   // 35
    const int base = t * CH;

    int sum = 0;
    #pragma unroll
    for (int i = 0; i < CH; i++) {
        const int idx = base + i;
        if (idx < NCELLS) sum += g_hist[idx];
    }
    s[t] = sum;
    __syncthreads();
    for (int off = 1; off < 1024; off <<= 1) {   // Hillis-Steele, uniform
        int v = (t >= off) ? s[t - off] : 0;
        __syncthreads();
        s[t] += v;
        __syncthreads();
    }
    int run = (t > 0) ? s[t - 1] : 0;            // exclusive prefix
    #pragma unroll
    for (int i = 0; i < CH; i++) {
        const int idx = base + i;
        if (idx < NCELLS) {
            const int h = g_hist[idx];
            g_offs[idx] = run;
            run += h;
        }
    }
}

// ================= 4. scatter (atomic-free: offs + rank) =================
__global__ void __launch_bounds__(256)
k_scatter(int n)
{
    const int p = blockIdx.x * blockDim.x + threadIdx.x;
    if (p >= n) return;
    const int key = g_key[p];
    if (key < 0) return;
    const int pos = g_offs[key] + g_rank[p];
    g_sorted[pos] = p;
    g_wts[pos]   = g_wt[p];      // reorder weights for coalesced gather reads
}

// ================= 5. fused zero-fill + gather =================
// blocks [0, zb)       : each warp checks 32 points (coalesced), zeroes masked-out
// blocks [zb, zb + cb) : warp per cell; corners in regs; lane-parallel prefetch
__global__ void __launch_bounds__(256)
k_gather(const float* __restrict__ bev, float* __restrict__ out,
         int n, int zb)
{
    const int lane = threadIdx.x & 31;
    const int wid  = threadIdx.x >> 5;

    if (blockIdx.x < zb) {
        // ---- zero-fill: 32 points per warp ----
        const int wbase = (blockIdx.x * 8 + wid) * 32;
        if (wbase >= n) return;
        const int pi  = wbase + lane;
        const int key = (pi < n) ? g_key[pi] : 0;    // coalesced
        unsigned m = __ballot_sync(FULL, key < 0);
        const float4 z = make_float4(0.f, 0.f, 0.f, 0.f);
        while (m) {
            const int j = __ffs(m) - 1;
            m &= m - 1;
            float4* op = reinterpret_cast<float4*>(out + (size_t)(wbase + j) * BEV_C);
            __stcs(op + lane,      z);
            __stcs(op + lane + 32, z);
        }
        return;
    }

    // ---- gather: warp per cell ----
    const int c = (blockIdx.x - zb) * 8 + wid;
    if (c >= NCELLS) return;
    const int cnt = g_hist[c];
    if (cnt == 0) return;
    const int start = g_offs[c];

    const int xf = c % BEV_W;
    const int yf = c / BEV_W;
    const int x1 = min(xf + 1, BEV_W - 1);
    const int y1 = min(yf + 1, BEV_H - 1);

    const float4* A  = reinterpret_cast<const float4*>(bev + ((size_t)yf * BEV_W + xf) * BEV_C);
    const float4* B  = reinterpret_cast<const float4*>(bev + ((size_t)y1 * BEV_W + xf) * BEV_C);
    const float4* Cc = reinterpret_cast<const float4*>(bev + ((size_t)yf * BEV_W + x1) * BEV_C);
    const float4* D  = reinterpret_cast<const float4*>(bev + ((size_t)y1 * BEV_W + x1) * BEV_C);

    // corner rows into registers (8 x LDG.128, independent of point data)
    const float4 a0 = __ldcg(A  + lane);
    const float4 b0 = __ldcg(B  + lane);
    const float4 c0 = __ldcg(Cc + lane);
    const float4 d0 = __ldcg(D  + lane);
    const float4 a1 = __ldcg(A  + lane + 32);
    const float4 b1 = __ldcg(B  + lane + 32);
    const float4 c1 = __ldcg(Cc + lane + 32);
    const float4 d1 = __ldcg(D  + lane + 32);

    for (int cs = 0; cs < cnt; cs += 32) {
        const int m2 = min(32, cnt - cs);
        // lane-parallel prefetch: 2 coalesced loads cover up to 32 points
        int    pid = 0;
        float4 wt  = make_float4(0.f, 0.f, 0.f, 0.f);
        if (lane < m2) {
            pid = g_sorted[start + cs + lane];
            wt  = g_wts[start + cs + lane];
        }
        for (int j = 0; j < m2; j++) {
            const int   p  = __shfl_sync(FULL, pid,  j);
            const float wa = __shfl_sync(FULL, wt.x, j);
            const float wb = __shfl_sync(FULL, wt.y, j);
            const float wc = __shfl_sync(FULL, wt.z, j);
            const float wd = __shfl_sync(FULL, wt.w, j);

            float4 o0, o1;
            o0.x = a0.x * wa + b0.x * wb + c0.x * wc + d0.x * wd;
            o0.y = a0.y * wa + b0.y * wb + c0.y * wc + d0.y * wd;
            o0.z = a0.z * wa + b0.z * wb + c0.z * wc + d0.z * wd;
            o0.w = a0.w * wa + b0.w * wb + c0.w * wc + d0.w * wd;
            o1.x = a1.x * wa + b1.x * wb + c1.x * wc + d1.x * wd;
            o1.y = a1.y * wa + b1.y * wb + c1.y * wc + d1.y * wd;
            o1.z = a1.z * wa + b1.z * wb + c1.z * wc + d1.z * wd;
            o1.w = a1.w * wa + b1.w * wb + c1.w * wc + d1.w * wd;

            float4* op = reinterpret_cast<float4*>(out + (size_t)p * BEV_C);
            __stcs(op + lane,      o0);
            __stcs(op + lane + 32, o1);
        }
    }
}

extern "C" void kernel_launch(void* const* d_in, const int* in_sizes, int n_in,
                              void* d_out, int out_size)
{
    const float* points = (const float*)d_in[0];
    const float* rois   = (const float*)d_in[1];
    const float* bev    = (const float*)d_in[2];
    float* out = (float*)d_out;

    const int n = in_sizes[0] / 3;   // fixed-shape problem; n <= MAXN

    const int zwarps = (n + 31) / 32;
    const int zb = (zwarps + 7) / 8;            // zero-check blocks
    const int cb = (NCELLS + 7) / 8;            // cell blocks

    k_init<<<(NCELLS + 255) / 256, 256>>>();
    k_phase1<<<(n + 255) / 256, 256>>>(points, rois, n);
    k_scan<<<1, 1024>>>();
    k_scatter<<<(n + 255) / 256, 256>>>(n);
    k_gather<<<zb + cb, 256>>>(bev, out, n, zb);
}

// round 9
// speedup vs baseline: 1.9771x; 1.6235x over previous
#include <cuda_runtime.h>
#include <cuda_bf16.h>
#include <math.h>

#define N_ROIS 128
#define BEV_H 188
#define BEV_W 188
#define BEV_C 256
#define THREADS 256
#define WARPS 8
#define FULL 0xFFFFFFFFu

__global__ void __launch_bounds__(THREADS)
vsa_fused_kernel(const float* __restrict__ points,
                 const float* __restrict__ rois,
                 const float* __restrict__ bev,
                 float* __restrict__ out,
                 int n)
{
    // ROI cache: (cx, cy, cz, radius = ||dims/2|| + 2.4)
    __shared__ float4 s_roi[N_ROIS];
    // Phase-1 -> phase-2 handoff, per warp per point
    __shared__ float4 s_wt[WARPS][32];   // bilinear weights
    __shared__ int4   s_off[WARPS][32];  // x0,x1,y0,y1 ; x0=-1 zero, x0=-2 skip

    if (threadIdx.x < N_ROIS) {
        const float* rp = rois + threadIdx.x * 7;
        const float hl = rp[3] * 0.5f;
        const float hw = rp[4] * 0.5f;
        const float hh = rp[5] * 0.5f;
        const float rad = sqrtf(hl * hl + hw * hw + hh * hh) + 2.4f;
        s_roi[threadIdx.x] = make_float4(rp[0], rp[1], rp[2], rad);
    }
    __syncthreads();

    const int w    = threadIdx.x >> 5;
    const int lane = threadIdx.x & 31;
    const int p    = blockIdx.x * THREADS + threadIdx.x;
    const bool valid = p < n;

    // ---------------- Phase 1: thread-per-point argmin ----------------
    float px = 0.f, py = 0.f, pz = 0.f;
    if (valid) {
        px = points[p * 3 + 0];
        py = points[p * 3 + 1];
        pz = points[p * 3 + 2];
    }

    float best = INFINITY;
    int bidx = 0;
    #pragma unroll 4
    for (int r = 0; r < N_ROIS; r++) {
        const float4 q = s_roi[r];     // warp-broadcast LDS.128
        const float dx = px - q.x;
        const float dy = py - q.y;
        const float dz = pz - q.z;
        const float d2 = dx * dx + dy * dy + dz * dz;
        if (d2 < best) { best = d2; bidx = r; }   // '<' -> first occurrence
    }
    const float rad  = s_roi[bidx].w;
    const bool  mask = valid && (sqrtf(best) < rad);

    int4   off;
    float4 wt = make_float4(0.f, 0.f, 0.f, 0.f);
    if (!valid) {
        off = make_int4(-2, 0, 0, 0);
    } else if (!mask) {
        off = make_int4(-1, 0, 0, 0);
    } else {
        // bit-faithful coords: two fp32 divides, floor, clamp
        const float xi = (px - 0.0f)   / 0.05f / 8.0f;
        const float yi = (py - -40.0f) / 0.05f / 8.0f;
        const int xf = (int)floorf(xi);
        const int yf = (int)floorf(yi);
        const int x0 = min(max(xf,     0), BEV_W - 1);
        const int x1 = min(max(xf + 1, 0), BEV_W - 1);
        const int y0 = min(max(yf,     0), BEV_H - 1);
        const int y1 = min(max(yf + 1, 0), BEV_H - 1);
        const float x0f = (float)x0, x1f = (float)x1;
        const float y0f = (float)y0, y1f = (float)y1;
        wt.x = (x1f - xi) * (y1f - yi);   // wa
        wt.y = (x1f - xi) * (yi - y0f);   // wb
        wt.z = (xi - x0f) * (y1f - yi);   // wc
        wt.w = (xi - x0f) * (yi - y0f);   // wd
        off = make_int4(x0, x1, y0, y1);
    }
    s_off[w][lane] = off;
    s_wt[w][lane]  = wt;
    __syncwarp();

    // ---------------- Phase 2: warp-per-point, PAIRED for MLP=16 ----------------
    const int pbase = blockIdx.x * THREADS + w * 32;
    const float4 z = make_float4(0.f, 0.f, 0.f, 0.f);

    for (int i = 0; i < 32; i += 2) {
        // params for both pair members (warp-uniform broadcasts)
        const int4   oA = s_off[w][i];
        const int4   oB = s_off[w][i + 1];
        const float4 wA = s_wt[w][i];
        const float4 wB = s_wt[w][i + 1];
        const bool gA = (oA.x >= 0);
        const bool gB = (oB.x >= 0);

        // ---- issue ALL loads for both points first (MLP up to 16) ----
        float4 a0, b0, c0, d0, a1, b1, c1, d1;   // point A
        float4 e0, f0, g0, h0, e1, f1, g1, h1;   // point B
        if (gA) {   // warp-uniform branch
            const float4* A  = reinterpret_cast<const float4*>(bev + ((size_t)oA.z * BEV_W + oA.x) * BEV_C);
            const float4* B  = reinterpret_cast<const float4*>(bev + ((size_t)oA.w * BEV_W + oA.x) * BEV_C);
            const float4* Cc = reinterpret_cast<const float4*>(bev + ((size_t)oA.z * BEV_W + oA.y) * BEV_C);
            const float4* D  = reinterpret_cast<const float4*>(bev + ((size_t)oA.w * BEV_W + oA.y) * BEV_C);
            a0 = __ldcg(A  + lane);  b0 = __ldcg(B  + lane);
            c0 = __ldcg(Cc + lane);  d0 = __ldcg(D  + lane);
            a1 = __ldcg(A  + lane + 32);  b1 = __ldcg(B  + lane + 32);
            c1 = __ldcg(Cc + lane + 32);  d1 = __ldcg(D  + lane + 32);
        }
        if (gB) {   // warp-uniform branch
            const float4* A  = reinterpret_cast<const float4*>(bev + ((size_t)oB.z * BEV_W + oB.x) * BEV_C);
            const float4* B  = reinterpret_cast<const float4*>(bev + ((size_t)oB.w * BEV_W + oB.x) * BEV_C);
            const float4* Cc = reinterpret_cast<const float4*>(bev + ((size_t)oB.z * BEV_W + oB.y) * BEV_C);
            const float4* D  = reinterpret_cast<const float4*>(bev + ((size_t)oB.w * BEV_W + oB.y) * BEV_C);
            e0 = __ldcg(A  + lane);  f0 = __ldcg(B  + lane);
            g0 = __ldcg(Cc + lane);  h0 = __ldcg(D  + lane);
            e1 = __ldcg(A  + lane + 32);  f1 = __ldcg(B  + lane + 32);
            g1 = __ldcg(Cc + lane + 32);  h1 = __ldcg(D  + lane + 32);
        }

        // ---- point A: compute + store ----
        if (gA) {
            float4* op = reinterpret_cast<float4*>(out + (size_t)(pbase + i) * BEV_C);
            float4 o0, o1;
            o0.x = a0.x * wA.x + b0.x * wA.y + c0.x * wA.z + d0.x * wA.w;
            o0.y = a0.y * wA.x + b0.y * wA.y + c0.y * wA.z + d0.y * wA.w;
            o0.z = a0.z * wA.x + b0.z * wA.y + c0.z * wA.z + d0.z * wA.w;
            o0.w = a0.w * wA.x + b0.w * wA.y + c0.w * wA.z + d0.w * wA.w;
            o1.x = a1.x * wA.x + b1.x * wA.y + c1.x * wA.z + d1.x * wA.w;
            o1.y = a1.y * wA.x + b1.y * wA.y + c1.y * wA.z + d1.y * wA.w;
            o1.z = a1.z * wA.x + b1.z * wA.y + c1.z * wA.z + d1.z * wA.w;
            o1.w = a1.w * wA.x + b1.w * wA.y + c1.w * wA.z + d1.w * wA.w;
            __stcs(op + lane,      o0);
            __stcs(op + lane + 32, o1);
        } else if (oA.x == -1) {
            float4* op = reinterpret_cast<float4*>(out + (size_t)(pbase + i) * BEV_C);
            __stcs(op + lane,      z);
            __stcs(op + lane + 32, z);
        }

        // ---- point B: compute + store ----
        if (gB) {
            float4* op = reinterpret_cast<float4*>(out + (size_t)(pbase + i + 1) * BEV_C);
            float4 o0, o1;
            o0.x = e0.x * wB.x + f0.x * wB.y + g0.x * wB.z + h0.x * wB.w;
            o0.y = e0.y * wB.x + f0.y * wB.y + g0.y * wB.z + h0.y * wB.w;
            o0.z = e0.z * wB.x + f0.z * wB.y + g0.z * wB.z + h0.z * wB.w;
            o0.w = e0.w * wB.x + f0.w * wB.y + g0.w * wB.z + h0.w * wB.w;
            o1.x = e1.x * wB.x + f1.x * wB.y + g1.x * wB.z + h1.x * wB.w;
            o1.y = e1.y * wB.x + f1.y * wB.y + g1.y * wB.z + h1.y * wB.w;
            o1.z = e1.z * wB.x + f1.z * wB.y + g1.z * wB.z + h1.z * wB.w;
            o1.w = e1.w * wB.x + f1.w * wB.y + g1.w * wB.z + h1.w * wB.w;
            __stcs(op + lane,      o0);
            __stcs(op + lane + 32, o1);
        } else if (oB.x == -1) {
            float4* op = reinterpret_cast<float4*>(out + (size_t)(pbase + i + 1) * BEV_C);
            __stcs(op + lane,      z);
            __stcs(op + lane + 32, z);
        }
    }
}

extern "C" void kernel_launch(void* const* d_in, const int* in_sizes, int n_in,
                              void* d_out, int out_size)
{
    const float* points = (const float*)d_in[0];
    const float* rois   = (const float*)d_in[1];
    const float* bev    = (const float*)d_in[2];
    float* out = (float*)d_out;

    const int n = in_sizes[0] / 3;
    const int blocks = (n + THREADS - 1) / THREADS;
    vsa_fused_kernel<<<blocks, THREADS>>>(points, rois, bev, out, n);
}